// round 15
// baseline (speedup 1.0000x reference)
#include <cuda_runtime.h>
#include <cuda_bf16.h>

#define IMG_H 512
#define NBANDS 8
#define BANDH 64           // 8*64 = 512, uniform bands
#define NIMG 96            // 32 batch * 3 channels
#define ROWV4 128          // float4 per row
#define NT 128
#define XSTR 132           // float4 stride per exchange row (2 pad + 128 + 2 pad)
#define ASTR 132           // float stride for aux arrays
#define NBLK (NBANDS * NIMG)   // 768
#define NPIX 25165824.0f

typedef unsigned long long ull;
#define F2FMA(d,a,b,c) asm("fma.rn.f32x2 %0,%1,%2,%3;" : "=l"(d) : "l"(a), "l"(b), "l"(c))
#define F2ADD(d,a,b)   asm("add.rn.f32x2 %0,%1,%2;"    : "=l"(d) : "l"(a), "l"(b))
#define F2MUL(d,a,b)   asm("mul.rn.f32x2 %0,%1,%2;"    : "=l"(d) : "l"(a), "l"(b))
#define F2PACK(d,lo,hi) asm("mov.b64 %0,{%1,%2};" : "=l"(d) : "f"(lo), "f"(hi))
#define F2UNPK(lo,hi,s) asm("mov.b64 {%0,%1},%2;" : "=f"(lo), "=f"(hi) : "l"(s))

__device__ float g_partial[NBLK];
__device__ unsigned int g_count;   // zero-init; last block resets to 0 each launch

__device__ __forceinline__ void horiz5(const float4* __restrict__ buf,
                                       const float* __restrict__ aL,
                                       const float* __restrict__ aF,
                                       int t, float c0, float c1, float c2, float c3,
                                       float H[4])
{
    float  aw = aL[t];          // col 4t-5 (stride-1, conflict-free)
    float4 b  = buf[t + 1];     // cols 4t-4 .. 4t-1
    float4 d  = buf[t + 3];     // cols 4t+4 .. 4t+7
    float  e  = aF[t + 4];      // col 4t+8 (stride-1, conflict-free)
    float h0 = aw + b.x + b.y + b.z + b.w + c0 + c1 + c2 + c3 + d.x + d.y;
    float h1 = h0 - aw  + d.z;
    float h2 = h1 - b.x + d.w;
    float h3 = h2 - b.y + e;
    H[0] = h0; H[1] = h1; H[2] = h2; H[3] = h3;
}

__global__ void __launch_bounds__(NT, 5) ssim_band_kernel(
    const float* __restrict__ pred, const float* __restrict__ targ,
    float* __restrict__ out)
{
    __shared__ float4 xch[2][4 * XSTR];    // 4 quantities: p, t, p^2+t^2, p*t
    __shared__ float  auxL[2][4 * ASTR];   // c3 copies (col 4t+3)
    __shared__ float  auxF[2][4 * ASTR];   // c0 copies (col 4t)
    __shared__ float  red[NT];
    __shared__ int    is_last;

    const int t    = threadIdx.x;
    const int img  = blockIdx.y;
    const int band = blockIdx.x;
    const int r0   = band * BANDH;
    const int steps = BANDH + 10;

    const float4* __restrict__ P  = (const float4*)pred + (size_t)img * (IMG_H * ROWV4);
    const float4* __restrict__ T4 = (const float4*)targ + (size_t)img * (IMG_H * ROWV4);

    // Zero halo pads: indices {0,1} (threads 0,1) and {130,131} (threads 126,127).
    if (t < 2) {
        #pragma unroll
        for (int b = 0; b < 2; ++b)
            #pragma unroll
            for (int q = 0; q < 4; ++q) {
                xch[b][q * XSTR + t] = make_float4(0.f, 0.f, 0.f, 0.f);
                auxL[b][q * ASTR + t] = 0.f;
                auxF[b][q * ASTR + t] = 0.f;
            }
    } else if (t >= 126) {
        #pragma unroll
        for (int b = 0; b < 2; ++b)
            #pragma unroll
            for (int q = 0; q < 4; ++q) {
                xch[b][q * XSTR + t + 4] = make_float4(0.f, 0.f, 0.f, 0.f);
                auxL[b][q * ASTR + t + 4] = 0.f;
                auxF[b][q * ASTR + t + 4] = 0.f;
            }
    }

    // 4 packed vertical accumulators x 2 pairs
    ull vp01=0, vp23=0, vt01=0, vt23=0, vss01=0, vss23=0, vpt01=0, vpt23=0;
    float acc = 0.f;

    ull negone2, two2, ntwo2, c242, c121, K1p, K2p;
    F2PACK(negone2, -1.f, -1.f);
    F2PACK(two2,     2.f,  2.f);
    F2PACK(ntwo2,   -2.f, -2.f);
    F2PACK(c242,   242.f, 242.f);
    F2PACK(c121,   121.f, 121.f);
    F2PACK(K1p, 1.4641f, 1.4641f);      // 0.01^2 * 121^2
    F2PACK(K2p, 13.1769f, 13.1769f);    // 0.03^2 * 121^2

    #pragma unroll 1
    for (int s = 0; s <= steps; ++s) {
        const bool do_load = (s < steps);
        const int iy  = r0 - 5 + s;
        const int iy2 = iy - 11;

        // 1) issue this step's loads early (consumed after part 2)
        float4 p4  = make_float4(0.f,0.f,0.f,0.f);
        float4 q4  = make_float4(0.f,0.f,0.f,0.f);
        float4 po4 = make_float4(0.f,0.f,0.f,0.f);
        float4 qo4 = make_float4(0.f,0.f,0.f,0.f);
        if (do_load && (unsigned)iy < IMG_H) {
            p4 = P[iy * ROWV4 + t];
            q4 = T4[iy * ROWV4 + t];
        }
        if (do_load && s >= 11 && (unsigned)iy2 < IMG_H) {
            po4 = P[iy2 * ROWV4 + t];   // L1/L2-resident (11 rows back)
            qo4 = T4[iy2 * ROWV4 + t];
        }

        // 2) horiz + SSIM for the row published at step s-1 (registers still match)
        if (s >= 11) {
            const float4* buf = xch[(s - 1) & 1];
            const float*  aLb = auxL[(s - 1) & 1];
            const float*  aFb = auxF[(s - 1) & 1];
            float a0, a1, a2, a3;
            float Hp[4], Ht[4], Hss[4], Hpt[4];
            F2UNPK(a0, a1, vp01);   F2UNPK(a2, a3, vp23);
            horiz5(buf + 0 * XSTR, aLb + 0 * ASTR, aFb + 0 * ASTR, t, a0, a1, a2, a3, Hp);
            F2UNPK(a0, a1, vt01);   F2UNPK(a2, a3, vt23);
            horiz5(buf + 1 * XSTR, aLb + 1 * ASTR, aFb + 1 * ASTR, t, a0, a1, a2, a3, Ht);
            F2UNPK(a0, a1, vss01);  F2UNPK(a2, a3, vss23);
            horiz5(buf + 2 * XSTR, aLb + 2 * ASTR, aFb + 2 * ASTR, t, a0, a1, a2, a3, Hss);
            F2UNPK(a0, a1, vpt01);  F2UNPK(a2, a3, vpt23);
            horiz5(buf + 3 * XSTR, aLb + 3 * ASTR, aFb + 3 * ASTR, t, a0, a1, a2, a3, Hpt);

            float n[4], dn[4];
            #pragma unroll
            for (int j = 0; j < 2; ++j) {
                ull Sp, St, Wss, Wpt;
                F2PACK(Sp,  Hp[2*j],  Hp[2*j+1]);
                F2PACK(St,  Ht[2*j],  Ht[2*j+1]);
                F2PACK(Wss, Hss[2*j], Hss[2*j+1]);
                F2PACK(Wpt, Hpt[2*j], Hpt[2*j+1]);
                ull pq, A, spq, tmp, Cc, B, X, D, N, Dd;
                F2MUL(pq, Sp, St);
                F2FMA(A, two2, pq, K1p);           // 2 Sp St + C1*121^2
                F2MUL(tmp, St, St);
                F2FMA(spq, Sp, Sp, tmp);           // Sp^2 + St^2
                F2ADD(Cc, spq, K1p);
                F2FMA(tmp, ntwo2, pq, K2p);
                F2FMA(B, c242, Wpt, tmp);          // 2(121 Spt - Sp St) + C2*121^2
                F2FMA(X, spq, negone2, K2p);
                F2FMA(D, c121, Wss, X);            // 121(Spp+Stt) - spq + C2*121^2
                F2MUL(N, A, B);
                F2MUL(Dd, Cc, D);
                F2UNPK(n[2*j],  n[2*j+1],  N);
                F2UNPK(dn[2*j], dn[2*j+1], Dd);
            }
            // one divide per 4 pixels
            float na = fmaf(n[0], dn[1], n[1] * dn[0]);
            float da = dn[0] * dn[1];
            float nb = fmaf(n[2], dn[3], n[3] * dn[2]);
            float db = dn[2] * dn[3];
            float nf = fmaf(na, db, nb * da);
            float df = da * db;
            acc += __fdividef(nf, df);
        }

        // 3) vertical window update (packed): vp, vt, vss = sum(p^2+t^2), vpt
        if (do_load) {
            ull pn01, pn23, tn01, tn23, po01, po23, to01, to23;
            F2PACK(pn01, p4.x, p4.y);   F2PACK(pn23, p4.z, p4.w);
            F2PACK(tn01, q4.x, q4.y);   F2PACK(tn23, q4.z, q4.w);
            F2PACK(po01, po4.x, po4.y); F2PACK(po23, po4.z, po4.w);
            F2PACK(to01, qo4.x, qo4.y); F2PACK(to23, qo4.z, qo4.w);
            ull npo01, npo23, nto01, nto23;
            F2MUL(npo01, po01, negone2); F2MUL(npo23, po23, negone2);
            F2MUL(nto01, to01, negone2); F2MUL(nto23, to23, negone2);

            F2ADD(vp01, vp01, pn01);   F2ADD(vp01, vp01, npo01);
            F2ADD(vp23, vp23, pn23);   F2ADD(vp23, vp23, npo23);
            F2ADD(vt01, vt01, tn01);   F2ADD(vt01, vt01, nto01);
            F2ADD(vt23, vt23, tn23);   F2ADD(vt23, vt23, nto23);
            F2FMA(vss01, pn01, pn01, vss01);  F2FMA(vss01, npo01, po01, vss01);
            F2FMA(vss01, tn01, tn01, vss01);  F2FMA(vss01, nto01, to01, vss01);
            F2FMA(vss23, pn23, pn23, vss23);  F2FMA(vss23, npo23, po23, vss23);
            F2FMA(vss23, tn23, tn23, vss23);  F2FMA(vss23, nto23, to23, vss23);
            F2FMA(vpt01, pn01, tn01, vpt01);  F2FMA(vpt01, npo01, to01, vpt01);
            F2FMA(vpt23, pn23, tn23, vpt23);  F2FMA(vpt23, npo23, to23, vpt23);
        }

        // 4) publish updated window sums
        if (s >= 10 && do_load) {
            float4* buf = xch[s & 1];
            float*  aL  = auxL[s & 1];
            float*  aF  = auxF[s & 1];
            float w0, w1, w2, w3;
            F2UNPK(w0, w1, vp01);   F2UNPK(w2, w3, vp23);
            buf[0*XSTR + 2 + t] = make_float4(w0, w1, w2, w3);
            aL[0*ASTR + 2 + t] = w3;  aF[0*ASTR + 2 + t] = w0;
            F2UNPK(w0, w1, vt01);   F2UNPK(w2, w3, vt23);
            buf[1*XSTR + 2 + t] = make_float4(w0, w1, w2, w3);
            aL[1*ASTR + 2 + t] = w3;  aF[1*ASTR + 2 + t] = w0;
            F2UNPK(w0, w1, vss01);  F2UNPK(w2, w3, vss23);
            buf[2*XSTR + 2 + t] = make_float4(w0, w1, w2, w3);
            aL[2*ASTR + 2 + t] = w3;  aF[2*ASTR + 2 + t] = w0;
            F2UNPK(w0, w1, vpt01);  F2UNPK(w2, w3, vpt23);
            buf[3*XSTR + 2 + t] = make_float4(w0, w1, w2, w3);
            aL[3*ASTR + 2 + t] = w3;  aF[3*ASTR + 2 + t] = w0;
        }
        if (s >= 10) __syncthreads();
    }

    // Deterministic block reduction
    red[t] = acc;
    __syncthreads();
    #pragma unroll
    for (int off = NT / 2; off > 0; off >>= 1) {
        if (t < off) red[t] += red[t + off];
        __syncthreads();
    }
    if (t == 0) {
        g_partial[img * NBANDS + band] = red[0];
        __threadfence();
        unsigned v = atomicAdd(&g_count, 1u);
        is_last = (v == NBLK - 1);
    }
    __syncthreads();

    // Last block folds all 768 partials in a fixed order (deterministic).
    if (is_last) {
        float s2 = 0.f;
        #pragma unroll
        for (int k = 0; k < NBLK / NT; ++k) s2 += g_partial[t + k * NT];
        red[t] = s2;
        __syncthreads();
        #pragma unroll
        for (int off = NT / 2; off > 0; off >>= 1) {
            if (t < off) red[t] += red[t + off];
            __syncthreads();
        }
        if (t == 0) {
            out[0] = 1.0f - red[0] / NPIX;
            g_count = 0;   // reset for next graph replay
        }
    }
}

extern "C" void kernel_launch(void* const* d_in, const int* in_sizes, int n_in,
                              void* d_out, int out_size)
{
    const float* pred = (const float*)d_in[0];
    const float* targ = (const float*)d_in[1];
    dim3 grid(NBANDS, NIMG);
    ssim_band_kernel<<<grid, NT>>>(pred, targ, (float*)d_out);
}

// round 16
// speedup vs baseline: 1.0583x; 1.0583x over previous
#include <cuda_runtime.h>
#include <cuda_bf16.h>

#define IMG_H 512
#define NBANDS 6
#define BANDH 86           // 5*86 + 82 = 512
#define NIMG 96            // 32 batch * 3 channels
#define ROWV4 128          // float4 per row
#define NT 128
#define NBLK (NBANDS * NIMG)   // 576
#define NPIX 25165824.0f

typedef unsigned long long ull;
#define F2FMA(d,a,b,c) asm("fma.rn.f32x2 %0,%1,%2,%3;" : "=l"(d) : "l"(a), "l"(b), "l"(c))
#define F2ADD(d,a,b)   asm("add.rn.f32x2 %0,%1,%2;"    : "=l"(d) : "l"(a), "l"(b))
#define F2MUL(d,a,b)   asm("mul.rn.f32x2 %0,%1,%2;"    : "=l"(d) : "l"(a), "l"(b))
#define F2PACK(d,lo,hi) asm("mov.b64 %0,{%1,%2};" : "=l"(d) : "f"(lo), "f"(hi))
#define F2UNPK(lo,hi,s) asm("mov.b64 {%0,%1},%2;" : "=f"(lo), "=f"(hi) : "l"(s))

__device__ float g_partial[NBLK];
__device__ unsigned int g_count;   // zero-init; last block resets to 0 each launch

// Packed vertical-window update for one 4-column group (2 f32x2 pairs per quantity).
__device__ __forceinline__ void upd4(ull& sp01, ull& sp23, ull& st01, ull& st23,
                                     ull& ss01, ull& ss23, ull& sx01, ull& sx23,
                                     float4 pn, float4 tn, float4 po, float4 to,
                                     ull negone2)
{
    ull pn01, pn23, tn01, tn23, po01, po23, to01, to23;
    F2PACK(pn01, pn.x, pn.y);  F2PACK(pn23, pn.z, pn.w);
    F2PACK(tn01, tn.x, tn.y);  F2PACK(tn23, tn.z, tn.w);
    F2PACK(po01, po.x, po.y);  F2PACK(po23, po.z, po.w);
    F2PACK(to01, to.x, to.y);  F2PACK(to23, to.z, to.w);
    ull npo01, npo23, nto01, nto23;
    F2MUL(npo01, po01, negone2); F2MUL(npo23, po23, negone2);
    F2MUL(nto01, to01, negone2); F2MUL(nto23, to23, negone2);

    F2ADD(sp01, sp01, pn01);   F2ADD(sp01, sp01, npo01);
    F2ADD(sp23, sp23, pn23);   F2ADD(sp23, sp23, npo23);
    F2ADD(st01, st01, tn01);   F2ADD(st01, st01, nto01);
    F2ADD(st23, st23, tn23);   F2ADD(st23, st23, nto23);
    F2FMA(ss01, pn01, pn01, ss01);  F2FMA(ss01, npo01, po01, ss01);
    F2FMA(ss01, tn01, tn01, ss01);  F2FMA(ss01, nto01, to01, ss01);
    F2FMA(ss23, pn23, pn23, ss23);  F2FMA(ss23, npo23, po23, ss23);
    F2FMA(ss23, tn23, tn23, ss23);  F2FMA(ss23, nto23, to23, ss23);
    F2FMA(sx01, pn01, tn01, sx01);  F2FMA(sx01, npo01, to01, sx01);
    F2FMA(sx23, pn23, tn23, sx23);  F2FMA(sx23, npo23, to23, sx23);
}

// Shuffle-based horizontal 11-tap for one quantity.
// v01,v23: this lane's own 4 window sums; h01,h23: this lane's halo-group sums.
// Boundary source lanes substitute their halo value (each such value has exactly
// one consumer, verified per tap).
__device__ __forceinline__ void horizq(unsigned lane, ull v01, ull v23,
                                       ull h01, ull h23, float H[4])
{
    const unsigned FULL = 0xFFFFFFFFu;
    ull sB01 = (lane == 31u) ? h01 : v01;
    ull sB23 = (lane == 31u) ? h23 : v23;
    ull b01 = __shfl_sync(FULL, sB01, (lane + 31) & 31);
    ull b23 = __shfl_sync(FULL, sB23, (lane + 31) & 31);
    ull sD01 = (lane == 0u) ? h01 : v01;
    ull sD23 = (lane == 0u) ? h23 : v23;
    ull d01 = __shfl_sync(FULL, sD01, (lane + 1) & 31);
    ull d23 = __shfl_sync(FULL, sD23, (lane + 1) & 31);

    float c0, c1, c2, c3;
    F2UNPK(c0, c1, v01);  F2UNPK(c2, c3, v23);
    float hc0, hc1, hc2, hc3;
    F2UNPK(hc0, hc1, h01);  F2UNPK(hc2, hc3, h23);

    float awsrc = (lane >= 30u) ? hc3 : c3;              // c3 of group lane-2
    float aw = __shfl_sync(FULL, awsrc, (lane + 30) & 31);
    float esrc = (lane < 2u) ? hc0 : c0;                 // c0 of group lane+2
    float e = __shfl_sync(FULL, esrc, (lane + 2) & 31);

    float b0, b1, b2, b3, d0, d1, d2, d3;
    F2UNPK(b0, b1, b01);  F2UNPK(b2, b3, b23);
    F2UNPK(d0, d1, d01);  F2UNPK(d2, d3, d23);

    float h0 = ((aw + b0) + (b1 + b2)) + (((b3 + c0) + (c1 + c2)) + ((c3 + d0) + d1));
    float h1 = h0 - aw + d2;
    float h2 = h1 - b0 + d3;
    float h3 = h2 - b1 + e;
    H[0] = h0; H[1] = h1; H[2] = h2; H[3] = h3;
}

__global__ void __launch_bounds__(NT, 4) ssim_band_kernel(
    const float* __restrict__ pred, const float* __restrict__ targ,
    float* __restrict__ out)
{
    __shared__ float red[NT];
    __shared__ int is_last;

    const int t    = threadIdx.x;
    const unsigned lane = t & 31;
    const int warp = t >> 5;
    const int img  = blockIdx.y;
    const int band = blockIdx.x;
    const int r0   = band * BANDH;
    const int h    = (band < NBANDS - 1) ? BANDH : (IMG_H - (NBANDS - 1) * BANDH);
    const int steps = h + 10;

    const float4* __restrict__ P  = (const float4*)pred + (size_t)img * (IMG_H * ROWV4);
    const float4* __restrict__ T4 = (const float4*)targ + (size_t)img * (IMG_H * ROWV4);

    // Column groups: warp owns groups [32w, 32w+32); halo groups for lanes:
    // lane0 -> +32, lane1 -> +33, lane30 -> -2, lane31 -> -1 (relative to strip).
    const int gOwn = warp * 32 + (int)lane;
    const int gHl  = (lane < 2u) ? (32 + (int)lane) : ((int)lane - 32);
    const int gHalo = warp * 32 + gHl;
    const bool haloLane = (lane < 2u) || (lane >= 30u);
    const bool haloOK = haloLane && ((unsigned)gHalo < (unsigned)ROWV4);

    // Own accumulators (4 quantities x 2 packed pairs) + halo accumulators.
    ull vp01=0, vp23=0, vt01=0, vt23=0, vs01=0, vs23=0, vx01=0, vx23=0;
    ull hp01=0, hp23=0, ht01=0, ht23=0, hs01=0, hs23=0, hx01=0, hx23=0;
    float acc = 0.f;

    ull negone2, two2, ntwo2, c242, c121, K1p, K2p;
    F2PACK(negone2, -1.f, -1.f);
    F2PACK(two2,     2.f,  2.f);
    F2PACK(ntwo2,   -2.f, -2.f);
    F2PACK(c242,   242.f, 242.f);
    F2PACK(c121,   121.f, 121.f);
    F2PACK(K1p, 1.4641f, 1.4641f);      // 0.01^2 * 121^2
    F2PACK(K2p, 13.1769f, 13.1769f);    // 0.03^2 * 121^2

    const float4 Z4 = make_float4(0.f, 0.f, 0.f, 0.f);

    // Prefetch row s=0 (iy = r0-5)
    float4 cp4 = Z4, ct4 = Z4, chp4 = Z4, cht4 = Z4;
    {
        const int iy = r0 - 5;
        if ((unsigned)iy < IMG_H) {
            cp4 = P[iy * ROWV4 + gOwn];
            ct4 = T4[iy * ROWV4 + gOwn];
            if (haloOK) {
                chp4 = P[iy * ROWV4 + gHalo];
                cht4 = T4[iy * ROWV4 + gHalo];
            }
        }
    }

    #pragma unroll 1
    for (int s = 0; s < steps; ++s) {
        const int iy  = r0 - 5 + s;
        const int iy2 = iy - 11;
        const int iyn = iy + 1;

        // Prefetch next new row (DRAM latency hidden across this iteration's math)
        float4 np4 = Z4, nt4 = Z4, nhp4 = Z4, nht4 = Z4;
        if (s + 1 < steps && (unsigned)iyn < IMG_H) {
            np4 = P[iyn * ROWV4 + gOwn];
            nt4 = T4[iyn * ROWV4 + gOwn];
            if (haloOK) {
                nhp4 = P[iyn * ROWV4 + gHalo];
                nht4 = T4[iyn * ROWV4 + gHalo];
            }
        }

        // Leaving row (L1/L2-resident: loaded 11 steps ago)
        float4 op4 = Z4, ot4 = Z4, ohp4 = Z4, oht4 = Z4;
        if (s >= 11 && (unsigned)iy2 < IMG_H) {
            op4 = P[iy2 * ROWV4 + gOwn];
            ot4 = T4[iy2 * ROWV4 + gOwn];
            if (haloOK) {
                ohp4 = P[iy2 * ROWV4 + gHalo];
                oht4 = T4[iy2 * ROWV4 + gHalo];
            }
        }

        // Vertical window update: own group, then halo group
        upd4(vp01, vp23, vt01, vt23, vs01, vs23, vx01, vx23,
             cp4, ct4, op4, ot4, negone2);
        upd4(hp01, hp23, ht01, ht23, hs01, hs23, hx01, hx23,
             chp4, cht4, ohp4, oht4, negone2);

        // Horizontal 11-tap + SSIM (no deferral, no barrier: shuffles only)
        if (s >= 10) {
            float Hp[4], Ht[4], Hss[4], Hpt[4];
            horizq(lane, vp01, vp23, hp01, hp23, Hp);
            horizq(lane, vt01, vt23, ht01, ht23, Ht);
            horizq(lane, vs01, vs23, hs01, hs23, Hss);
            horizq(lane, vx01, vx23, hx01, hx23, Hpt);

            float n[4], dn[4];
            #pragma unroll
            for (int j = 0; j < 2; ++j) {
                ull Sp, St, Wss, Wpt;
                F2PACK(Sp,  Hp[2*j],  Hp[2*j+1]);
                F2PACK(St,  Ht[2*j],  Ht[2*j+1]);
                F2PACK(Wss, Hss[2*j], Hss[2*j+1]);
                F2PACK(Wpt, Hpt[2*j], Hpt[2*j+1]);
                ull pq, A, spq, tmp, Cc, B, X, D, N, Dd;
                F2MUL(pq, Sp, St);
                F2FMA(A, two2, pq, K1p);           // 2 Sp St + C1*121^2
                F2MUL(tmp, St, St);
                F2FMA(spq, Sp, Sp, tmp);           // Sp^2 + St^2
                F2ADD(Cc, spq, K1p);
                F2FMA(tmp, ntwo2, pq, K2p);
                F2FMA(B, c242, Wpt, tmp);          // 2(121 Spt - Sp St) + C2*121^2
                F2FMA(X, spq, negone2, K2p);
                F2FMA(D, c121, Wss, X);            // 121(Spp+Stt) - spq + C2*121^2
                F2MUL(N, A, B);
                F2MUL(Dd, Cc, D);
                F2UNPK(n[2*j],  n[2*j+1],  N);
                F2UNPK(dn[2*j], dn[2*j+1], Dd);
            }
            // one divide per 4 pixels
            float na = fmaf(n[0], dn[1], n[1] * dn[0]);
            float da = dn[0] * dn[1];
            float nb = fmaf(n[2], dn[3], n[3] * dn[2]);
            float db = dn[2] * dn[3];
            float nf = fmaf(na, db, nb * da);
            float df = da * db;
            acc += __fdividef(nf, df);
        }

        cp4 = np4;  ct4 = nt4;  chp4 = nhp4;  cht4 = nht4;
    }

    // Deterministic block reduction
    red[t] = acc;
    __syncthreads();
    #pragma unroll
    for (int off = NT / 2; off > 0; off >>= 1) {
        if (t < off) red[t] += red[t + off];
        __syncthreads();
    }
    if (t == 0) {
        g_partial[img * NBANDS + band] = red[0];
        __threadfence();
        unsigned v = atomicAdd(&g_count, 1u);
        is_last = (v == NBLK - 1);
    }
    __syncthreads();

    // Last block folds all 576 partials in a fixed order (deterministic).
    if (is_last) {
        float s2 = g_partial[t] + g_partial[t + 128] + g_partial[t + 256] + g_partial[t + 384];
        if (t < NBLK - 512) s2 += g_partial[t + 512];
        red[t] = s2;
        __syncthreads();
        #pragma unroll
        for (int off = NT / 2; off > 0; off >>= 1) {
            if (t < off) red[t] += red[t + off];
            __syncthreads();
        }
        if (t == 0) {
            out[0] = 1.0f - red[0] / NPIX;
            g_count = 0;   // reset for next graph replay
        }
    }
}

extern "C" void kernel_launch(void* const* d_in, const int* in_sizes, int n_in,
                              void* d_out, int out_size)
{
    const float* pred = (const float*)d_in[0];
    const float* targ = (const float*)d_in[1];
    dim3 grid(NBANDS, NIMG);
    ssim_band_kernel<<<grid, NT>>>(pred, targ, (float*)d_out);
}

// round 17
// speedup vs baseline: 1.4029x; 1.3256x over previous
#include <cuda_runtime.h>
#include <cuda_bf16.h>

#define IMG_H 512
#define NBANDS 6
#define BANDH 86           // 5*86 + 82 = 512
#define NIMG 96            // 32 batch * 3 channels
#define ROWV4 128          // float4 per row
#define NT 128
#define XSTR 132           // float4 stride per exchange row (2 pad + 128 + 2 pad)
#define NBLK (NBANDS * NIMG)   // 576
#define NPIX 25165824.0f

typedef unsigned long long ull;
#define F2FMA(d,a,b,c) asm("fma.rn.f32x2 %0,%1,%2,%3;" : "=l"(d) : "l"(a), "l"(b), "l"(c))
#define F2ADD(d,a,b)   asm("add.rn.f32x2 %0,%1,%2;"    : "=l"(d) : "l"(a), "l"(b))
#define F2MUL(d,a,b)   asm("mul.rn.f32x2 %0,%1,%2;"    : "=l"(d) : "l"(a), "l"(b))
#define F2PACK(d,lo,hi) asm("mov.b64 %0,{%1,%2};" : "=l"(d) : "f"(lo), "f"(hi))
#define F2UNPK(lo,hi,s) asm("mov.b64 {%0,%1},%2;" : "=f"(lo), "=f"(hi) : "l"(s))

__device__ float g_partial[NBLK];
__device__ unsigned int g_count;   // zero-init; last block resets to 0 each launch

// Packed vertical-window update (4 quantities x 2 f32x2 pairs).
__device__ __forceinline__ void upd4(ull& sp01, ull& sp23, ull& st01, ull& st23,
                                     ull& ss01, ull& ss23, ull& sx01, ull& sx23,
                                     float4 pn, float4 tn, float4 po, float4 to,
                                     ull negone2)
{
    ull pn01, pn23, tn01, tn23, po01, po23, to01, to23;
    F2PACK(pn01, pn.x, pn.y);  F2PACK(pn23, pn.z, pn.w);
    F2PACK(tn01, tn.x, tn.y);  F2PACK(tn23, tn.z, tn.w);
    F2PACK(po01, po.x, po.y);  F2PACK(po23, po.z, po.w);
    F2PACK(to01, to.x, to.y);  F2PACK(to23, to.z, to.w);
    ull npo01, npo23, nto01, nto23;
    F2MUL(npo01, po01, negone2); F2MUL(npo23, po23, negone2);
    F2MUL(nto01, to01, negone2); F2MUL(nto23, to23, negone2);

    F2ADD(sp01, sp01, pn01);   F2ADD(sp01, sp01, npo01);
    F2ADD(sp23, sp23, pn23);   F2ADD(sp23, sp23, npo23);
    F2ADD(st01, st01, tn01);   F2ADD(st01, st01, nto01);
    F2ADD(st23, st23, tn23);   F2ADD(st23, st23, nto23);
    F2FMA(ss01, pn01, pn01, ss01);  F2FMA(ss01, npo01, po01, ss01);
    F2FMA(ss01, tn01, tn01, ss01);  F2FMA(ss01, nto01, to01, ss01);
    F2FMA(ss23, pn23, pn23, ss23);  F2FMA(ss23, npo23, po23, ss23);
    F2FMA(ss23, tn23, tn23, ss23);  F2FMA(ss23, nto23, to23, ss23);
    F2FMA(sx01, pn01, tn01, sx01);  F2FMA(sx01, npo01, to01, sx01);
    F2FMA(sx23, pn23, tn23, sx23);  F2FMA(sx23, npo23, to23, sx23);
}

// 11-tap horizontal sliding sum; all 4 smem reads are LDS.128, conflict-free.
__device__ __forceinline__ void horiz4(const float4* __restrict__ row, int t,
                                       float c0, float c1, float c2, float c3,
                                       float H[4])
{
    float4 a  = row[t];         // cols 4t-8 .. 4t-5 (use .w)
    float4 b  = row[t + 1];     // cols 4t-4 .. 4t-1
    float4 d  = row[t + 3];     // cols 4t+4 .. 4t+7
    float4 ee = row[t + 4];     // cols 4t+8 .. 4t+11 (use .x)
    float h0 = ((a.w + b.x) + (b.y + b.z))
             + (((b.w + c0) + (c1 + c2)) + ((c3 + d.x) + d.y));
    float h1 = h0 - a.w + d.z;
    float h2 = h1 - b.x + d.w;
    float h3 = h2 - b.y + ee.x;
    H[0] = h0; H[1] = h1; H[2] = h2; H[3] = h3;
}

// Publish 4 quantities' window sums for one row-slot.
__device__ __forceinline__ void publish(float4* brow, int t,
                                        ull a01, ull a23, ull b01, ull b23,
                                        ull c01, ull c23, ull d01, ull d23)
{
    float w0, w1, w2, w3;
    F2UNPK(w0, w1, a01);  F2UNPK(w2, w3, a23);
    brow[0 * XSTR + 2 + t] = make_float4(w0, w1, w2, w3);
    F2UNPK(w0, w1, b01);  F2UNPK(w2, w3, b23);
    brow[1 * XSTR + 2 + t] = make_float4(w0, w1, w2, w3);
    F2UNPK(w0, w1, c01);  F2UNPK(w2, w3, c23);
    brow[2 * XSTR + 2 + t] = make_float4(w0, w1, w2, w3);
    F2UNPK(w0, w1, d01);  F2UNPK(w2, w3, d23);
    brow[3 * XSTR + 2 + t] = make_float4(w0, w1, w2, w3);
}

// Horizontal pass + SSIM map for one output row; returns 4-pixel contribution.
__device__ __forceinline__ float row_ssim(const float4* __restrict__ brow, int t,
    ull p01, ull p23, ull q01, ull q23, ull s01, ull s23, ull x01, ull x23,
    ull two2, ull ntwo2, ull negone2, ull c242, ull c121, ull K1p, ull K2p)
{
    float a0, a1, a2, a3;
    float Hp[4], Ht[4], Hss[4], Hpt[4];
    F2UNPK(a0, a1, p01);  F2UNPK(a2, a3, p23);
    horiz4(brow + 0 * XSTR, t, a0, a1, a2, a3, Hp);
    F2UNPK(a0, a1, q01);  F2UNPK(a2, a3, q23);
    horiz4(brow + 1 * XSTR, t, a0, a1, a2, a3, Ht);
    F2UNPK(a0, a1, s01);  F2UNPK(a2, a3, s23);
    horiz4(brow + 2 * XSTR, t, a0, a1, a2, a3, Hss);
    F2UNPK(a0, a1, x01);  F2UNPK(a2, a3, x23);
    horiz4(brow + 3 * XSTR, t, a0, a1, a2, a3, Hpt);

    float n[4], dn[4];
    #pragma unroll
    for (int j = 0; j < 2; ++j) {
        ull Sp, St, Wss, Wpt;
        F2PACK(Sp,  Hp[2*j],  Hp[2*j+1]);
        F2PACK(St,  Ht[2*j],  Ht[2*j+1]);
        F2PACK(Wss, Hss[2*j], Hss[2*j+1]);
        F2PACK(Wpt, Hpt[2*j], Hpt[2*j+1]);
        ull pq, A, spq, tmp, Cc, B, X, D, N, Dd;
        F2MUL(pq, Sp, St);
        F2FMA(A, two2, pq, K1p);           // 2 Sp St + C1*121^2
        F2MUL(tmp, St, St);
        F2FMA(spq, Sp, Sp, tmp);           // Sp^2 + St^2
        F2ADD(Cc, spq, K1p);
        F2FMA(tmp, ntwo2, pq, K2p);
        F2FMA(B, c242, Wpt, tmp);          // 2(121 Spt - Sp St) + C2*121^2
        F2FMA(X, spq, negone2, K2p);
        F2FMA(D, c121, Wss, X);            // 121(Spp+Stt) - spq + C2*121^2
        F2MUL(N, A, B);
        F2MUL(Dd, Cc, D);
        F2UNPK(n[2*j],  n[2*j+1],  N);
        F2UNPK(dn[2*j], dn[2*j+1], Dd);
    }
    float na = fmaf(n[0], dn[1], n[1] * dn[0]);
    float da = dn[0] * dn[1];
    float nb = fmaf(n[2], dn[3], n[3] * dn[2]);
    float db = dn[2] * dn[3];
    float nf = fmaf(na, db, nb * da);
    float df = da * db;
    return __fdividef(nf, df);
}

__global__ void __launch_bounds__(NT, 4) ssim_band_kernel(
    const float* __restrict__ pred, const float* __restrict__ targ,
    float* __restrict__ out)
{
    __shared__ float4 xch[2][2][4 * XSTR];   // [pair buffer][row in pair][quantity] (33.8 KB)
    __shared__ float  red[NT];
    __shared__ int    is_last;

    const int t    = threadIdx.x;
    const int img  = blockIdx.y;
    const int band = blockIdx.x;
    const int r0   = band * BANDH;
    const int h    = (band < NBANDS - 1) ? BANDH : (IMG_H - (NBANDS - 1) * BANDH);
    const int K    = (h + 10) >> 1;    // pairs; h+10 is even (96 or 92)

    const float4* __restrict__ P  = (const float4*)pred + (size_t)img * (IMG_H * ROWV4);
    const float4* __restrict__ T4 = (const float4*)targ + (size_t)img * (IMG_H * ROWV4);

    // Zero the 64 pad float4s (idx 0,1,130,131 per quantity-row, both buffers+rows).
    if (t < 64) {
        int buf = t >> 5, row = (t >> 4) & 1, q = (t >> 2) & 3, pi = t & 3;
        xch[buf][row][q * XSTR + ((pi < 2) ? pi : 128 + pi)] =
            make_float4(0.f, 0.f, 0.f, 0.f);
    }

    ull vp01=0, vp23=0, vt01=0, vt23=0, vs01=0, vs23=0, vx01=0, vx23=0;
    ull sp01=0, sp23=0, st01=0, st23=0, ss01=0, ss23=0, sx01=0, sx23=0;  // row-A snapshot
    float acc = 0.f;

    ull negone2, two2, ntwo2, c242, c121, K1p, K2p;
    F2PACK(negone2, -1.f, -1.f);
    F2PACK(two2,     2.f,  2.f);
    F2PACK(ntwo2,   -2.f, -2.f);
    F2PACK(c242,   242.f, 242.f);
    F2PACK(c121,   121.f, 121.f);
    F2PACK(K1p, 1.4641f, 1.4641f);      // 0.01^2 * 121^2
    F2PACK(K2p, 13.1769f, 13.1769f);    // 0.03^2 * 121^2

    const float4 Z4 = make_float4(0.f, 0.f, 0.f, 0.f);

    #pragma unroll 1
    for (int k = 0; k <= K; ++k) {
        const bool do_load = (k < K);
        const int s0  = 2 * k;
        const int iyA = r0 - 5 + s0;     // pair's first entering row
        const int iyB = iyA + 1;

        // 1) issue NEW-row loads now; consumed after the compute block (latency hidden)
        float4 pA = Z4, tA = Z4, pB = Z4, tB = Z4;
        if (do_load) {
            if ((unsigned)iyA < IMG_H) { pA = P[iyA * ROWV4 + t]; tA = T4[iyA * ROWV4 + t]; }
            if ((unsigned)iyB < IMG_H) { pB = P[iyB * ROWV4 + t]; tB = T4[iyB * ROWV4 + t]; }
        }

        // 2) compute pair k-1 (published last iteration; registers/snapshot still match)
        if (k >= 6) {
            const float4* b0 = xch[(k - 1) & 1][0];
            const float4* b1 = xch[(k - 1) & 1][1];
            acc += row_ssim(b0, t, sp01, sp23, st01, st23, ss01, ss23, sx01, sx23,
                            two2, ntwo2, negone2, c242, c121, K1p, K2p);
            acc += row_ssim(b1, t, vp01, vp23, vt01, vt23, vs01, vs23, vx01, vx23,
                            two2, ntwo2, negone2, c242, c121, K1p, K2p);
        }

        // 3) leaving-row loads (L1/L2-resident), then vertical updates + publish
        if (do_load) {
            const int iyA2 = iyA - 11, iyB2 = iyB - 11;
            float4 poA = Z4, toA = Z4, poB = Z4, toB = Z4;
            if (s0 >= 11 && (unsigned)iyA2 < IMG_H) {
                poA = P[iyA2 * ROWV4 + t];  toA = T4[iyA2 * ROWV4 + t];
            }
            if (s0 + 1 >= 11 && (unsigned)iyB2 < IMG_H) {
                poB = P[iyB2 * ROWV4 + t];  toB = T4[iyB2 * ROWV4 + t];
            }

            upd4(vp01, vp23, vt01, vt23, vs01, vs23, vx01, vx23, pA, tA, poA, toA, negone2);
            if (k >= 5)
                publish(xch[k & 1][0], t, vp01, vp23, vt01, vt23, vs01, vs23, vx01, vx23);
            // snapshot row-A state for next iteration's compute
            sp01 = vp01; sp23 = vp23; st01 = vt01; st23 = vt23;
            ss01 = vs01; ss23 = vs23; sx01 = vx01; sx23 = vx23;

            upd4(vp01, vp23, vt01, vt23, vs01, vs23, vx01, vx23, pB, tB, poB, toB, negone2);
            if (k >= 5)
                publish(xch[k & 1][1], t, vp01, vp23, vt01, vt23, vs01, vs23, vx01, vx23);
        }

        if (k >= 5) __syncthreads();   // one barrier per 2 rows
    }

    // Deterministic block reduction
    red[t] = acc;
    __syncthreads();
    #pragma unroll
    for (int off = NT / 2; off > 0; off >>= 1) {
        if (t < off) red[t] += red[t + off];
        __syncthreads();
    }
    if (t == 0) {
        g_partial[img * NBANDS + band] = red[0];
        __threadfence();
        unsigned v = atomicAdd(&g_count, 1u);
        is_last = (v == NBLK - 1);
    }
    __syncthreads();

    // Last block folds all 576 partials in a fixed order (deterministic).
    if (is_last) {
        float s2 = g_partial[t] + g_partial[t + 128] + g_partial[t + 256] + g_partial[t + 384];
        if (t < NBLK - 512) s2 += g_partial[t + 512];
        red[t] = s2;
        __syncthreads();
        #pragma unroll
        for (int off = NT / 2; off > 0; off >>= 1) {
            if (t < off) red[t] += red[t + off];
            __syncthreads();
        }
        if (t == 0) {
            out[0] = 1.0f - red[0] / NPIX;
            g_count = 0;   // reset for next graph replay
        }
    }
}

extern "C" void kernel_launch(void* const* d_in, const int* in_sizes, int n_in,
                              void* d_out, int out_size)
{
    const float* pred = (const float*)d_in[0];
    const float* targ = (const float*)d_in[1];
    dim3 grid(NBANDS, NIMG);
    ssim_band_kernel<<<grid, NT>>>(pred, targ, (float*)d_out);
}